// round 6
// baseline (speedup 1.0000x reference)
#include <cuda_runtime.h>
#include <cuda_bf16.h>
#include <math_constants.h>
#include <cstdint>

#define NB   64
#define LL   577
#define DD   512
#define EE   1024
#define HH   512
#define KSEL 288
#define MM   (NB * KSEL)        // 18432 rows
#define NPART 576

// ---------------- scratch (static device globals; no allocation) -------------
__device__ __align__(16) __nv_bfloat16 g_Ahi[(size_t)MM * 1024]; // cols 0-511: relu_bn_h, 512-1023: feats
__device__ __align__(16) __nv_bfloat16 g_Alo[(size_t)MM * 1024];
__device__ __align__(16) float g_h[(size_t)MM * 512];
__device__ __align__(16) __nv_bfloat16 g_Whi[1024 * 1024];  // [e][k] k<512: w1, else fc_w
__device__ __align__(16) __nv_bfloat16 g_Wlo[1024 * 1024];
__device__ __align__(16) __nv_bfloat16 g_W0hi[512 * 512];
__device__ __align__(16) __nv_bfloat16 g_W0lo[512 * 512];
__device__ __align__(16) float g_bias2[1024];
__device__ __align__(16) float g_psum[NPART * 512];
__device__ __align__(16) float g_psq [NPART * 512];
__device__ __align__(16) float g_scale[512];
__device__ __align__(16) float g_shift[512];
__device__ int g_sel[NB * KSEL];

// ---------------- helpers ----------------------------------------------------
__device__ __forceinline__ uint32_t smem_u32(const void* p) {
    uint32_t a;
    asm("{ .reg .u64 t; cvta.to.shared.u64 t, %1; cvt.u32.u64 %0, t; }" : "=r"(a) : "l"(p));
    return a;
}
__device__ __forceinline__ void cp_async16(uint32_t saddr, const void* gaddr) {
    asm volatile("cp.async.cg.shared.global [%0], [%1], 16;" :: "r"(saddr), "l"(gaddr));
}
#define CP_COMMIT() asm volatile("cp.async.commit_group;" ::: "memory")
#define CP_WAIT1()  asm volatile("cp.async.wait_group 1;" ::: "memory")

__device__ __forceinline__ void ldsm_x4(uint32_t& r0, uint32_t& r1, uint32_t& r2, uint32_t& r3,
                                        uint32_t addr) {
    asm volatile("ldmatrix.sync.aligned.m8n8.x4.shared.b16 {%0,%1,%2,%3}, [%4];"
                 : "=r"(r0), "=r"(r1), "=r"(r2), "=r"(r3) : "r"(addr));
}
__device__ __forceinline__ void mma_bf16(float& d0, float& d1, float& d2, float& d3,
                                         uint32_t a0, uint32_t a1, uint32_t a2, uint32_t a3,
                                         uint32_t b0, uint32_t b1) {
    asm volatile("mma.sync.aligned.m16n8k16.row.col.f32.bf16.bf16.f32 "
                 "{%0,%1,%2,%3}, {%4,%5,%6,%7}, {%8,%9}, {%0,%1,%2,%3};"
                 : "+f"(d0), "+f"(d1), "+f"(d2), "+f"(d3)
                 : "r"(a0), "r"(a1), "r"(a2), "r"(a3), "r"(b0), "r"(b1));
}
__device__ __forceinline__ void atomicMaxFloat(float* addr, float val) {
    if (__float_as_int(val) >= 0) atomicMax((int*)addr, __float_as_int(val));
    else atomicMin((unsigned int*)addr, __float_as_uint(val));
}

// ---------------- small kernels ----------------------------------------------
__global__ void init_out_kernel(float* __restrict__ out) {
    int i = blockIdx.x * blockDim.x + threadIdx.x;
    if (i < NB * EE) out[i] = -CUDART_INF_F;
}

__global__ void topk_kernel(const float* __restrict__ atten) {
    __shared__ float s[LL];
    const int b = blockIdx.x;
    const float* __restrict__ row = atten + (size_t)b * LL * LL;
    for (int i = threadIdx.x; i < LL; i += blockDim.x)
        s[i] = (i == 0) ? -1.0f : row[i];
    __syncthreads();
    for (int i = threadIdx.x; i < LL; i += blockDim.x) {
        const float si = s[i];
        int rank = 0;
        #pragma unroll 4
        for (int j = 0; j < LL; ++j) {
            const float sj = s[j];
            rank += (sj > si) || (sj == si && j < i);
        }
        if (rank < KSEL) g_sel[b * KSEL + rank] = i;
    }
}

__global__ void gather_split_kernel(const float* __restrict__ basef) {
    const int t = blockIdx.x, b = blockIdx.y;
    const int n = b * KSEL + t;
    const int tok = g_sel[n];
    const float4* src = (const float4*)(basef + ((size_t)b * LL + tok) * DD);
    const float4 v = src[threadIdx.x];
    float ss = v.x * v.x + v.y * v.y + v.z * v.z + v.w * v.w;
    #pragma unroll
    for (int off = 16; off > 0; off >>= 1)
        ss += __shfl_xor_sync(0xffffffffu, ss, off);
    __shared__ float wsum[4];
    const int lane = threadIdx.x & 31, wid = threadIdx.x >> 5;
    if (lane == 0) wsum[wid] = ss;
    __syncthreads();
    const float tot = wsum[0] + wsum[1] + wsum[2] + wsum[3];
    const float inv = 1.0f / (sqrtf(tot) + 1e-8f);
    float f[4] = {v.x * inv, v.y * inv, v.z * inv, v.w * inv};
    __nv_bfloat16 hi[4], lo[4];
    #pragma unroll
    for (int i = 0; i < 4; ++i) {
        hi[i] = __float2bfloat16_rn(f[i]);
        lo[i] = __float2bfloat16_rn(f[i] - __bfloat162float(hi[i]));
    }
    const size_t off = (size_t)n * 1024 + 512 + threadIdx.x * 4;
    *(uint2*)(g_Ahi + off) = *(uint2*)hi;
    *(uint2*)(g_Alo + off) = *(uint2*)lo;
}

__global__ void split_w0_kernel(const float* __restrict__ w0) {
    const int i = blockIdx.x * blockDim.x + threadIdx.x;
    if (i >= 512 * 512) return;
    const float w = w0[i];
    const __nv_bfloat16 hi = __float2bfloat16_rn(w);
    g_W0hi[i] = hi;
    g_W0lo[i] = __float2bfloat16_rn(w - __bfloat162float(hi));
}
__global__ void split_wcat_kernel(const float* __restrict__ w1, const float* __restrict__ fcw) {
    const int i = blockIdx.x * blockDim.x + threadIdx.x;
    if (i >= 1024 * 1024) return;
    const int e = i >> 10, k = i & 1023;
    const float w = (k < 512) ? w1[e * 512 + k] : fcw[e * 512 + (k - 512)];
    const __nv_bfloat16 hi = __float2bfloat16_rn(w);
    g_Whi[i] = hi;
    g_Wlo[i] = __float2bfloat16_rn(w - __bfloat162float(hi));
}
__global__ void bias2_kernel(const float* __restrict__ b1, const float* __restrict__ bfc) {
    const int i = blockIdx.x * blockDim.x + threadIdx.x;
    if (i < 1024) g_bias2[i] = b1[i] + bfc[i];
}

// ---------------- HMMA GEMM (bf16 split, 3 accumulating passes) --------------
// Block 128x128, K-tile 32, 3-stage cp.async pipeline, 8 warps (2 M x 4 N).
// GRID: blockIdx.x = N-block (few), blockIdx.y = M-block (many), so a resident
// wave spans ALL N-blocks x few M-blocks -> A tiles + all W stay hot in L2.
// EPI 0: out[row*ldo+col] = acc + bias[col]
// EPI 1: fused per-batch (KSEL rows) max via atomicMaxFloat into out (init -inf)
#define STAGE_BYTES 32768
#define SMEM_DYN (3 * STAGE_BYTES + 128)
extern __shared__ char dynsm[];

template<int EPI>
__global__ void __launch_bounds__(256) hmma_gemm_kernel(
    const __nv_bfloat16* __restrict__ aHi, const __nv_bfloat16* __restrict__ aLo, int lda,
    const __nv_bfloat16* __restrict__ bHi, const __nv_bfloat16* __restrict__ bLo, int ldb,
    const float* __restrict__ bias, float* __restrict__ out, int ldo, int KT) {
    const int tid  = threadIdx.x;
    const int lane = tid & 31;
    const int wid  = tid >> 5;
    const int warp_m = wid & 1;      // 2 warps along M (64 each)
    const int warp_n = wid >> 1;     // 4 warps along N (32 each)
    const int m0 = blockIdx.y * 128; // M-block: slow grid dim (L2 reuse)
    const int n0 = blockIdx.x * 128; // N-block: fast grid dim

    const uint32_t tb = (smem_u32(dynsm) + 127u) & ~127u;

    // loader: this thread's two 16B chunks per 8KB sub-tile
    const int u0 = tid, u1 = tid + 256;
    const int lr0 = u0 >> 2, lc0 = u0 & 3;
    const int lr1 = u1 >> 2, lc1 = u1 & 3;
    const uint32_t so0 = (uint32_t)(lr0 * 64 + ((lc0 ^ ((lr0 >> 1) & 3)) << 4));
    const uint32_t so1 = (uint32_t)(lr1 * 64 + ((lc1 ^ ((lr1 >> 1) & 3)) << 4));

    auto load_stage = [&](int stage, int kt) {
        const uint32_t sb = tb + stage * STAGE_BYTES;
        const int k0 = kt * 32;
        const size_t ga0 = (size_t)(m0 + lr0) * lda + k0 + lc0 * 8;
        const size_t ga1 = (size_t)(m0 + lr1) * lda + k0 + lc1 * 8;
        const size_t gb0 = (size_t)(n0 + lr0) * ldb + k0 + lc0 * 8;
        const size_t gb1 = (size_t)(n0 + lr1) * ldb + k0 + lc1 * 8;
        cp_async16(sb + so0,         aHi + ga0);
        cp_async16(sb + so1,         aHi + ga1);
        cp_async16(sb + 8192 + so0,  aLo + ga0);
        cp_async16(sb + 8192 + so1,  aLo + ga1);
        cp_async16(sb + 16384 + so0, bHi + gb0);
        cp_async16(sb + 16384 + so1, bHi + gb1);
        cp_async16(sb + 24576 + so0, bLo + gb0);
        cp_async16(sb + 24576 + so1, bLo + gb1);
    };

    float acc[4][4][4];
    #pragma unroll
    for (int i = 0; i < 4; ++i)
        #pragma unroll
        for (int j = 0; j < 4; ++j)
            #pragma unroll
            for (int q = 0; q < 4; ++q) acc[i][j][q] = 0.f;

    const int aRow = warp_m * 64 + (lane & 15);
    const int aSwz = (aRow >> 1) & 3;
    const int bRow = warp_n * 32 + (lane & 15);
    const int bSwz = (bRow >> 1) & 3;
    const int cHalf = lane >> 4;

    load_stage(0, 0); CP_COMMIT();
    load_stage(1, 1); CP_COMMIT();

    for (int kt = 0; kt < KT; ++kt) {
        CP_WAIT1();
        __syncthreads();
        if (kt + 2 < KT) load_stage((kt + 2) % 3, kt + 2);
        CP_COMMIT();

        const uint32_t sb = tb + (kt % 3) * STAGE_BYTES;
        #pragma unroll
        for (int pass = 0; pass < 3; ++pass) {
            const uint32_t sA = sb + (pass == 1 ? 8192u : 0u);
            const uint32_t sB = sb + 16384u + (pass == 2 ? 8192u : 0u);
            #pragma unroll
            for (int ks = 0; ks < 2; ++ks) {
                const int c = 2 * ks + cHalf;
                const uint32_t aco = (uint32_t)((c ^ aSwz) << 4);
                const uint32_t bco = (uint32_t)((c ^ bSwz) << 4);
                uint32_t a[4][4];
                #pragma unroll
                for (int mt = 0; mt < 4; ++mt)
                    ldsm_x4(a[mt][0], a[mt][1], a[mt][2], a[mt][3],
                            sA + (uint32_t)((aRow + mt * 16) * 64) + aco);
                uint32_t b[2][4];
                #pragma unroll
                for (int nt = 0; nt < 2; ++nt)
                    ldsm_x4(b[nt][0], b[nt][1], b[nt][2], b[nt][3],
                            sB + (uint32_t)((bRow + nt * 16) * 64) + bco);
                #pragma unroll
                for (int mt = 0; mt < 4; ++mt) {
                    #pragma unroll
                    for (int n8 = 0; n8 < 4; ++n8) {
                        const int nt = n8 >> 1, nl = n8 & 1;
                        mma_bf16(acc[mt][n8][0], acc[mt][n8][1], acc[mt][n8][2], acc[mt][n8][3],
                                 a[mt][0], a[mt][1], a[mt][2], a[mt][3],
                                 b[nt][nl], b[nt][nl + 2]);
                    }
                }
            }
        }
    }

    // ------------- epilogue -------------
    const int colBase = n0 + warp_n * 32 + 2 * (lane & 3);
    const int rowBase = m0 + warp_m * 64 + (lane >> 2);
    if (EPI == 0) {
        #pragma unroll
        for (int n8 = 0; n8 < 4; ++n8) {
            const int col = colBase + n8 * 8;
            const float bv0 = __ldg(&bias[col]);
            const float bv1 = __ldg(&bias[col + 1]);
            #pragma unroll
            for (int mt = 0; mt < 4; ++mt) {
                const int r = rowBase + mt * 16;
                float2 v0 = {acc[mt][n8][0] + bv0, acc[mt][n8][1] + bv1};
                float2 v1 = {acc[mt][n8][2] + bv0, acc[mt][n8][3] + bv1};
                *(float2*)(out + (size_t)r * ldo + col) = v0;
                *(float2*)(out + (size_t)(r + 8) * ldo + col) = v1;
            }
        }
    } else {
        #pragma unroll
        for (int n8 = 0; n8 < 4; ++n8) {
            #pragma unroll
            for (int j = 0; j < 2; ++j) {
                const int col = colBase + n8 * 8 + j;
                const float bv = __ldg(&bias[col]);
                float m = -CUDART_INF_F;
                int curb = -1;
                #pragma unroll
                for (int mt = 0; mt < 4; ++mt) {
                    #pragma unroll
                    for (int half = 0; half < 2; ++half) {
                        const int r = rowBase + mt * 16 + half * 8;
                        const int bb = r / KSEL;
                        const float v = acc[mt][n8][half * 2 + j] + bv;
                        if (bb != curb) {
                            if (curb >= 0) atomicMaxFloat(&out[curb * EE + col], m);
                            curb = bb;
                            m = v;
                        } else {
                            m = fmaxf(m, v);
                        }
                    }
                }
                atomicMaxFloat(&out[curb * EE + col], m);
            }
        }
    }
}

// ---------------- BN stats / BN+ReLU+split -----------------------------------
__global__ void stats_partial_kernel() {
    const int c4 = threadIdx.x;
    const int r0 = blockIdx.x * 32;
    float4 s = {0.f, 0.f, 0.f, 0.f}, q = {0.f, 0.f, 0.f, 0.f};
    #pragma unroll 4
    for (int r = 0; r < 32; ++r) {
        float4 v = *(const float4*)(g_h + (size_t)(r0 + r) * 512 + c4 * 4);
        s.x += v.x; s.y += v.y; s.z += v.z; s.w += v.w;
        q.x += v.x * v.x; q.y += v.y * v.y; q.z += v.z * v.z; q.w += v.w * v.w;
    }
    *(float4*)(g_psum + blockIdx.x * 512 + c4 * 4) = s;
    *(float4*)(g_psq  + blockIdx.x * 512 + c4 * 4) = q;
}
__global__ void stats_finalize_kernel(const float* __restrict__ gamma,
                                      const float* __restrict__ beta) {
    const int c = blockIdx.x * 128 + threadIdx.x;
    float s = 0.f, q = 0.f;
    for (int p = 0; p < NPART; ++p) {
        s += g_psum[p * 512 + c];
        q += g_psq [p * 512 + c];
    }
    const float invN = 1.0f / (float)MM;
    const float mean = s * invN;
    const float var  = q * invN - mean * mean;
    const float sc = gamma[c] * rsqrtf(var + 1e-5f);
    g_scale[c] = sc;
    g_shift[c] = beta[c] - mean * sc;
}
__global__ void bnrelu_split_kernel() {
    const int idx = blockIdx.x * blockDim.x + threadIdx.x;
    const int n = idx >> 7, c4 = idx & 127;
    float4 v = *(const float4*)(g_h + (size_t)n * 512 + c4 * 4);
    const float4 sc = *(const float4*)(g_scale + c4 * 4);
    const float4 sh = *(const float4*)(g_shift + c4 * 4);
    float y[4];
    y[0] = fmaxf(fmaf(v.x, sc.x, sh.x), 0.f);
    y[1] = fmaxf(fmaf(v.y, sc.y, sh.y), 0.f);
    y[2] = fmaxf(fmaf(v.z, sc.z, sh.z), 0.f);
    y[3] = fmaxf(fmaf(v.w, sc.w, sh.w), 0.f);
    __nv_bfloat16 hi[4], lo[4];
    #pragma unroll
    for (int i = 0; i < 4; ++i) {
        hi[i] = __float2bfloat16_rn(y[i]);
        lo[i] = __float2bfloat16_rn(y[i] - __bfloat162float(hi[i]));
    }
    const size_t off = (size_t)n * 1024 + c4 * 4;
    *(uint2*)(g_Ahi + off) = *(uint2*)hi;
    *(uint2*)(g_Alo + off) = *(uint2*)lo;
}

// ---------------- launch ------------------------------------------------------
extern "C" void kernel_launch(void* const* d_in, const int* in_sizes, int n_in,
                              void* d_out, int out_size) {
    const float* basef = (const float*)d_in[0];
    const float* atten = (const float*)d_in[1];
    const float* fc_w  = (const float*)d_in[2];
    const float* fc_b  = (const float*)d_in[3];
    const float* w0    = (const float*)d_in[4];
    const float* b0    = (const float*)d_in[5];
    const float* gamma = (const float*)d_in[6];
    const float* beta  = (const float*)d_in[7];
    const float* w1    = (const float*)d_in[8];
    const float* b1    = (const float*)d_in[9];
    float* out = (float*)d_out;

    cudaFuncSetAttribute(hmma_gemm_kernel<0>, cudaFuncAttributeMaxDynamicSharedMemorySize, SMEM_DYN);
    cudaFuncSetAttribute(hmma_gemm_kernel<1>, cudaFuncAttributeMaxDynamicSharedMemorySize, SMEM_DYN);

    void *pAhi, *pAlo, *pW0hi, *pW0lo, *pWhi, *pWlo, *pB2, *pH;
    cudaGetSymbolAddress(&pAhi, g_Ahi);
    cudaGetSymbolAddress(&pAlo, g_Alo);
    cudaGetSymbolAddress(&pW0hi, g_W0hi);
    cudaGetSymbolAddress(&pW0lo, g_W0lo);
    cudaGetSymbolAddress(&pWhi, g_Whi);
    cudaGetSymbolAddress(&pWlo, g_Wlo);
    cudaGetSymbolAddress(&pB2, g_bias2);
    cudaGetSymbolAddress(&pH, g_h);

    // launch order chosen so index 3 (empirically what ncu captures) is gemm1
    topk_kernel<<<NB, 256>>>(atten);                       // 0
    gather_split_kernel<<<dim3(KSEL, NB), 128>>>(basef);   // 1
    split_w0_kernel<<<1024, 256>>>(w0);                    // 2

    // GEMM1: h = feats @ w0^T + b0  (grid x=N-blocks, y=M-blocks for L2 reuse)
    hmma_gemm_kernel<0><<<dim3(HH / 128, MM / 128), 256, SMEM_DYN>>>(   // 3
        (const __nv_bfloat16*)pAhi + 512, (const __nv_bfloat16*)pAlo + 512, 1024,
        (const __nv_bfloat16*)pW0hi, (const __nv_bfloat16*)pW0lo, 512,
        b0, (float*)pH, 512, 16);

    split_wcat_kernel<<<4096, 256>>>(w1, fc_w);            // 4
    bias2_kernel<<<4, 256>>>(b1, fc_b);                    // 5
    stats_partial_kernel<<<NPART, 128>>>();                // 6
    stats_finalize_kernel<<<4, 128>>>(gamma, beta);        // 7
    bnrelu_split_kernel<<<(MM * 128) / 256, 256>>>();      // 8
    init_out_kernel<<<(NB * EE + 255) / 256, 256>>>(out);  // 9

    // GEMM2: fused max of [relu_bn_h | feats] @ [w1 | fc_w]^T + (b1+fc_b)
    hmma_gemm_kernel<1><<<dim3(EE / 128, MM / 128), 256, SMEM_DYN>>>(   // 10
        (const __nv_bfloat16*)pAhi, (const __nv_bfloat16*)pAlo, 1024,
        (const __nv_bfloat16*)pWhi, (const __nv_bfloat16*)pWlo, 1024,
        (const float*)pB2, out, EE, 32);
}

// round 7
// speedup vs baseline: 1.0268x; 1.0268x over previous
#include <cuda_runtime.h>
#include <cuda_bf16.h>
#include <math_constants.h>
#include <cstdint>

#define NB   64
#define LL   577
#define DD   512
#define EE   1024
#define HH   512
#define KSEL 288
#define MM   (NB * KSEL)        // 18432 rows
#define NPART 576

// ---------------- scratch (static device globals; no allocation) -------------
__device__ __align__(16) __nv_bfloat16 g_Ahi[(size_t)MM * 1024]; // cols 0-511: relu_bn_h, 512-1023: feats
__device__ __align__(16) __nv_bfloat16 g_Alo[(size_t)MM * 1024];
__device__ __align__(16) float g_h[(size_t)MM * 512];
__device__ __align__(16) __nv_bfloat16 g_Whi[1024 * 1024];  // [e][k] k<512: w1, else fc_w
__device__ __align__(16) __nv_bfloat16 g_Wlo[1024 * 1024];
__device__ __align__(16) __nv_bfloat16 g_W0hi[512 * 512];
__device__ __align__(16) __nv_bfloat16 g_W0lo[512 * 512];
__device__ __align__(16) float g_bias2[1024];
__device__ __align__(16) float g_psum[NPART * 512];
__device__ __align__(16) float g_psq [NPART * 512];
__device__ __align__(16) float g_scale[512];
__device__ __align__(16) float g_shift[512];
__device__ int g_sel[NB * KSEL];

// ---------------- helpers ----------------------------------------------------
__device__ __forceinline__ uint32_t smem_u32(const void* p) {
    uint32_t a;
    asm("{ .reg .u64 t; cvta.to.shared.u64 t, %1; cvt.u32.u64 %0, t; }" : "=r"(a) : "l"(p));
    return a;
}
__device__ __forceinline__ void cp_async16(uint32_t saddr, const void* gaddr) {
    asm volatile("cp.async.cg.shared.global [%0], [%1], 16;" :: "r"(saddr), "l"(gaddr));
}
#define CP_COMMIT() asm volatile("cp.async.commit_group;" ::: "memory")
#define CP_WAIT1()  asm volatile("cp.async.wait_group 1;" ::: "memory")

__device__ __forceinline__ void ldsm_x4(uint32_t& r0, uint32_t& r1, uint32_t& r2, uint32_t& r3,
                                        uint32_t addr) {
    asm volatile("ldmatrix.sync.aligned.m8n8.x4.shared.b16 {%0,%1,%2,%3}, [%4];"
                 : "=r"(r0), "=r"(r1), "=r"(r2), "=r"(r3) : "r"(addr));
}
__device__ __forceinline__ void mma_bf16(float& d0, float& d1, float& d2, float& d3,
                                         uint32_t a0, uint32_t a1, uint32_t a2, uint32_t a3,
                                         uint32_t b0, uint32_t b1) {
    asm volatile("mma.sync.aligned.m16n8k16.row.col.f32.bf16.bf16.f32 "
                 "{%0,%1,%2,%3}, {%4,%5,%6,%7}, {%8,%9}, {%0,%1,%2,%3};"
                 : "+f"(d0), "+f"(d1), "+f"(d2), "+f"(d3)
                 : "r"(a0), "r"(a1), "r"(a2), "r"(a3), "r"(b0), "r"(b1));
}
__device__ __forceinline__ void atomicMaxFloat(float* addr, float val) {
    if (__float_as_int(val) >= 0) atomicMax((int*)addr, __float_as_int(val));
    else atomicMin((unsigned int*)addr, __float_as_uint(val));
}

// ---------------- small kernels ----------------------------------------------
__global__ void init_out_kernel(float* __restrict__ out) {
    int i = blockIdx.x * blockDim.x + threadIdx.x;
    if (i < NB * EE) out[i] = -CUDART_INF_F;
}

__global__ void topk_kernel(const float* __restrict__ atten) {
    __shared__ float s[LL];
    const int b = blockIdx.x;
    const float* __restrict__ row = atten + (size_t)b * LL * LL;
    for (int i = threadIdx.x; i < LL; i += blockDim.x)
        s[i] = (i == 0) ? -1.0f : row[i];
    __syncthreads();
    for (int i = threadIdx.x; i < LL; i += blockDim.x) {
        const float si = s[i];
        int rank = 0;
        #pragma unroll 4
        for (int j = 0; j < LL; ++j) {
            const float sj = s[j];
            rank += (sj > si) || (sj == si && j < i);
        }
        if (rank < KSEL) g_sel[b * KSEL + rank] = i;
    }
}

__global__ void gather_split_kernel(const float* __restrict__ basef) {
    const int t = blockIdx.x, b = blockIdx.y;
    const int n = b * KSEL + t;
    const int tok = g_sel[n];
    const float4* src = (const float4*)(basef + ((size_t)b * LL + tok) * DD);
    const float4 v = src[threadIdx.x];
    float ss = v.x * v.x + v.y * v.y + v.z * v.z + v.w * v.w;
    #pragma unroll
    for (int off = 16; off > 0; off >>= 1)
        ss += __shfl_xor_sync(0xffffffffu, ss, off);
    __shared__ float wsum[4];
    const int lane = threadIdx.x & 31, wid = threadIdx.x >> 5;
    if (lane == 0) wsum[wid] = ss;
    __syncthreads();
    const float tot = wsum[0] + wsum[1] + wsum[2] + wsum[3];
    const float inv = 1.0f / (sqrtf(tot) + 1e-8f);
    float f[4] = {v.x * inv, v.y * inv, v.z * inv, v.w * inv};
    __nv_bfloat16 hi[4], lo[4];
    #pragma unroll
    for (int i = 0; i < 4; ++i) {
        hi[i] = __float2bfloat16_rn(f[i]);
        lo[i] = __float2bfloat16_rn(f[i] - __bfloat162float(hi[i]));
    }
    const size_t off = (size_t)n * 1024 + 512 + threadIdx.x * 4;
    *(uint2*)(g_Ahi + off) = *(uint2*)hi;
    *(uint2*)(g_Alo + off) = *(uint2*)lo;
}

__global__ void split_w0_kernel(const float* __restrict__ w0) {
    const int i = blockIdx.x * blockDim.x + threadIdx.x;
    if (i >= 512 * 512) return;
    const float w = w0[i];
    const __nv_bfloat16 hi = __float2bfloat16_rn(w);
    g_W0hi[i] = hi;
    g_W0lo[i] = __float2bfloat16_rn(w - __bfloat162float(hi));
}
__global__ void split_wcat_kernel(const float* __restrict__ w1, const float* __restrict__ fcw) {
    const int i = blockIdx.x * blockDim.x + threadIdx.x;
    if (i >= 1024 * 1024) return;
    const int e = i >> 10, k = i & 1023;
    const float w = (k < 512) ? w1[e * 512 + k] : fcw[e * 512 + (k - 512)];
    const __nv_bfloat16 hi = __float2bfloat16_rn(w);
    g_Whi[i] = hi;
    g_Wlo[i] = __float2bfloat16_rn(w - __bfloat162float(hi));
}
__global__ void bias2_kernel(const float* __restrict__ b1, const float* __restrict__ bfc) {
    const int i = blockIdx.x * blockDim.x + threadIdx.x;
    if (i < 1024) g_bias2[i] = b1[i] + bfc[i];
}

// ---------------- HMMA GEMM (bf16 split, 3 accumulating passes) --------------
// Block 128x128, K-tile 32, 3-stage cp.async pipeline, 8 warps (2 M x 4 N).
// __launch_bounds__(256, 2): cap regs at 128 so TWO CTAs fit per SM
// (2 x 96KB smem = 192KB <= 228KB). Doubles warps/SMSP: 2 -> 4, hiding the
// LDSM->MMA latency chain and the per-ktile sync drain that held tensor at 49%.
// EPI 0: out[row*ldo+col] = acc + bias[col]
// EPI 1: fused per-batch (KSEL rows) max via atomicMaxFloat into out (init -inf)
#define STAGE_BYTES 32768
#define SMEM_DYN (3 * STAGE_BYTES + 128)
extern __shared__ char dynsm[];

template<int EPI>
__global__ void __launch_bounds__(256, 2) hmma_gemm_kernel(
    const __nv_bfloat16* __restrict__ aHi, const __nv_bfloat16* __restrict__ aLo, int lda,
    const __nv_bfloat16* __restrict__ bHi, const __nv_bfloat16* __restrict__ bLo, int ldb,
    const float* __restrict__ bias, float* __restrict__ out, int ldo, int KT) {
    const int tid  = threadIdx.x;
    const int lane = tid & 31;
    const int wid  = tid >> 5;
    const int warp_m = wid & 1;      // 2 warps along M (64 each)
    const int warp_n = wid >> 1;     // 4 warps along N (32 each)
    const int m0 = blockIdx.y * 128; // M-block: slow grid dim
    const int n0 = blockIdx.x * 128; // N-block: fast grid dim

    const uint32_t tb = (smem_u32(dynsm) + 127u) & ~127u;

    // loader: this thread's two 16B chunks per 8KB sub-tile
    const int u0 = tid, u1 = tid + 256;
    const int lr0 = u0 >> 2, lc0 = u0 & 3;
    const int lr1 = u1 >> 2, lc1 = u1 & 3;
    const uint32_t so0 = (uint32_t)(lr0 * 64 + ((lc0 ^ ((lr0 >> 1) & 3)) << 4));
    const uint32_t so1 = (uint32_t)(lr1 * 64 + ((lc1 ^ ((lr1 >> 1) & 3)) << 4));

    auto load_stage = [&](int stage, int kt) {
        const uint32_t sb = tb + stage * STAGE_BYTES;
        const int k0 = kt * 32;
        const size_t ga0 = (size_t)(m0 + lr0) * lda + k0 + lc0 * 8;
        const size_t ga1 = (size_t)(m0 + lr1) * lda + k0 + lc1 * 8;
        const size_t gb0 = (size_t)(n0 + lr0) * ldb + k0 + lc0 * 8;
        const size_t gb1 = (size_t)(n0 + lr1) * ldb + k0 + lc1 * 8;
        cp_async16(sb + so0,         aHi + ga0);
        cp_async16(sb + so1,         aHi + ga1);
        cp_async16(sb + 8192 + so0,  aLo + ga0);
        cp_async16(sb + 8192 + so1,  aLo + ga1);
        cp_async16(sb + 16384 + so0, bHi + gb0);
        cp_async16(sb + 16384 + so1, bHi + gb1);
        cp_async16(sb + 24576 + so0, bLo + gb0);
        cp_async16(sb + 24576 + so1, bLo + gb1);
    };

    float acc[4][4][4];
    #pragma unroll
    for (int i = 0; i < 4; ++i)
        #pragma unroll
        for (int j = 0; j < 4; ++j)
            #pragma unroll
            for (int q = 0; q < 4; ++q) acc[i][j][q] = 0.f;

    const int aRow = warp_m * 64 + (lane & 15);
    const int aSwz = (aRow >> 1) & 3;
    const int bRow = warp_n * 32 + (lane & 15);
    const int bSwz = (bRow >> 1) & 3;
    const int cHalf = lane >> 4;

    load_stage(0, 0); CP_COMMIT();
    load_stage(1, 1); CP_COMMIT();

    for (int kt = 0; kt < KT; ++kt) {
        CP_WAIT1();
        __syncthreads();
        if (kt + 2 < KT) load_stage((kt + 2) % 3, kt + 2);
        CP_COMMIT();

        const uint32_t sb = tb + (kt % 3) * STAGE_BYTES;
        #pragma unroll
        for (int pass = 0; pass < 3; ++pass) {
            const uint32_t sA = sb + (pass == 1 ? 8192u : 0u);
            const uint32_t sB = sb + 16384u + (pass == 2 ? 8192u : 0u);
            #pragma unroll
            for (int ks = 0; ks < 2; ++ks) {
                const int c = 2 * ks + cHalf;
                const uint32_t aco = (uint32_t)((c ^ aSwz) << 4);
                const uint32_t bco = (uint32_t)((c ^ bSwz) << 4);
                uint32_t a[4][4];
                #pragma unroll
                for (int mt = 0; mt < 4; ++mt)
                    ldsm_x4(a[mt][0], a[mt][1], a[mt][2], a[mt][3],
                            sA + (uint32_t)((aRow + mt * 16) * 64) + aco);
                uint32_t b[2][4];
                #pragma unroll
                for (int nt = 0; nt < 2; ++nt)
                    ldsm_x4(b[nt][0], b[nt][1], b[nt][2], b[nt][3],
                            sB + (uint32_t)((bRow + nt * 16) * 64) + bco);
                #pragma unroll
                for (int mt = 0; mt < 4; ++mt) {
                    #pragma unroll
                    for (int n8 = 0; n8 < 4; ++n8) {
                        const int nt = n8 >> 1, nl = n8 & 1;
                        mma_bf16(acc[mt][n8][0], acc[mt][n8][1], acc[mt][n8][2], acc[mt][n8][3],
                                 a[mt][0], a[mt][1], a[mt][2], a[mt][3],
                                 b[nt][nl], b[nt][nl + 2]);
                    }
                }
            }
        }
    }

    // ------------- epilogue -------------
    const int colBase = n0 + warp_n * 32 + 2 * (lane & 3);
    const int rowBase = m0 + warp_m * 64 + (lane >> 2);
    if (EPI == 0) {
        #pragma unroll
        for (int n8 = 0; n8 < 4; ++n8) {
            const int col = colBase + n8 * 8;
            const float bv0 = __ldg(&bias[col]);
            const float bv1 = __ldg(&bias[col + 1]);
            #pragma unroll
            for (int mt = 0; mt < 4; ++mt) {
                const int r = rowBase + mt * 16;
                float2 v0 = {acc[mt][n8][0] + bv0, acc[mt][n8][1] + bv1};
                float2 v1 = {acc[mt][n8][2] + bv0, acc[mt][n8][3] + bv1};
                *(float2*)(out + (size_t)r * ldo + col) = v0;
                *(float2*)(out + (size_t)(r + 8) * ldo + col) = v1;
            }
        }
    } else {
        #pragma unroll
        for (int n8 = 0; n8 < 4; ++n8) {
            #pragma unroll
            for (int j = 0; j < 2; ++j) {
                const int col = colBase + n8 * 8 + j;
                const float bv = __ldg(&bias[col]);
                float m = -CUDART_INF_F;
                int curb = -1;
                #pragma unroll
                for (int mt = 0; mt < 4; ++mt) {
                    #pragma unroll
                    for (int half = 0; half < 2; ++half) {
                        const int r = rowBase + mt * 16 + half * 8;
                        const int bb = r / KSEL;
                        const float v = acc[mt][n8][half * 2 + j] + bv;
                        if (bb != curb) {
                            if (curb >= 0) atomicMaxFloat(&out[curb * EE + col], m);
                            curb = bb;
                            m = v;
                        } else {
                            m = fmaxf(m, v);
                        }
                    }
                }
                atomicMaxFloat(&out[curb * EE + col], m);
            }
        }
    }
}

// ---------------- BN stats / BN+ReLU+split -----------------------------------
__global__ void stats_partial_kernel() {
    const int c4 = threadIdx.x;
    const int r0 = blockIdx.x * 32;
    float4 s = {0.f, 0.f, 0.f, 0.f}, q = {0.f, 0.f, 0.f, 0.f};
    #pragma unroll 4
    for (int r = 0; r < 32; ++r) {
        float4 v = *(const float4*)(g_h + (size_t)(r0 + r) * 512 + c4 * 4);
        s.x += v.x; s.y += v.y; s.z += v.z; s.w += v.w;
        q.x += v.x * v.x; q.y += v.y * v.y; q.z += v.z * v.z; q.w += v.w * v.w;
    }
    *(float4*)(g_psum + blockIdx.x * 512 + c4 * 4) = s;
    *(float4*)(g_psq  + blockIdx.x * 512 + c4 * 4) = q;
}
__global__ void stats_finalize_kernel(const float* __restrict__ gamma,
                                      const float* __restrict__ beta) {
    const int c = blockIdx.x * 128 + threadIdx.x;
    float s = 0.f, q = 0.f;
    for (int p = 0; p < NPART; ++p) {
        s += g_psum[p * 512 + c];
        q += g_psq [p * 512 + c];
    }
    const float invN = 1.0f / (float)MM;
    const float mean = s * invN;
    const float var  = q * invN - mean * mean;
    const float sc = gamma[c] * rsqrtf(var + 1e-5f);
    g_scale[c] = sc;
    g_shift[c] = beta[c] - mean * sc;
}
__global__ void bnrelu_split_kernel() {
    const int idx = blockIdx.x * blockDim.x + threadIdx.x;
    const int n = idx >> 7, c4 = idx & 127;
    float4 v = *(const float4*)(g_h + (size_t)n * 512 + c4 * 4);
    const float4 sc = *(const float4*)(g_scale + c4 * 4);
    const float4 sh = *(const float4*)(g_shift + c4 * 4);
    float y[4];
    y[0] = fmaxf(fmaf(v.x, sc.x, sh.x), 0.f);
    y[1] = fmaxf(fmaf(v.y, sc.y, sh.y), 0.f);
    y[2] = fmaxf(fmaf(v.z, sc.z, sh.z), 0.f);
    y[3] = fmaxf(fmaf(v.w, sc.w, sh.w), 0.f);
    __nv_bfloat16 hi[4], lo[4];
    #pragma unroll
    for (int i = 0; i < 4; ++i) {
        hi[i] = __float2bfloat16_rn(y[i]);
        lo[i] = __float2bfloat16_rn(y[i] - __bfloat162float(hi[i]));
    }
    const size_t off = (size_t)n * 1024 + c4 * 4;
    *(uint2*)(g_Ahi + off) = *(uint2*)hi;
    *(uint2*)(g_Alo + off) = *(uint2*)lo;
}

// ---------------- launch ------------------------------------------------------
extern "C" void kernel_launch(void* const* d_in, const int* in_sizes, int n_in,
                              void* d_out, int out_size) {
    const float* basef = (const float*)d_in[0];
    const float* atten = (const float*)d_in[1];
    const float* fc_w  = (const float*)d_in[2];
    const float* fc_b  = (const float*)d_in[3];
    const float* w0    = (const float*)d_in[4];
    const float* b0    = (const float*)d_in[5];
    const float* gamma = (const float*)d_in[6];
    const float* beta  = (const float*)d_in[7];
    const float* w1    = (const float*)d_in[8];
    const float* b1    = (const float*)d_in[9];
    float* out = (float*)d_out;

    cudaFuncSetAttribute(hmma_gemm_kernel<0>, cudaFuncAttributeMaxDynamicSharedMemorySize, SMEM_DYN);
    cudaFuncSetAttribute(hmma_gemm_kernel<1>, cudaFuncAttributeMaxDynamicSharedMemorySize, SMEM_DYN);

    void *pAhi, *pAlo, *pW0hi, *pW0lo, *pWhi, *pWlo, *pB2, *pH;
    cudaGetSymbolAddress(&pAhi, g_Ahi);
    cudaGetSymbolAddress(&pAlo, g_Alo);
    cudaGetSymbolAddress(&pW0hi, g_W0hi);
    cudaGetSymbolAddress(&pW0lo, g_W0lo);
    cudaGetSymbolAddress(&pWhi, g_Whi);
    cudaGetSymbolAddress(&pWlo, g_Wlo);
    cudaGetSymbolAddress(&pB2, g_bias2);
    cudaGetSymbolAddress(&pH, g_h);

    // launch order chosen so index 3 (empirically what ncu captures) is gemm1
    topk_kernel<<<NB, 256>>>(atten);                       // 0
    gather_split_kernel<<<dim3(KSEL, NB), 128>>>(basef);   // 1
    split_w0_kernel<<<1024, 256>>>(w0);                    // 2

    // GEMM1: h = feats @ w0^T + b0
    hmma_gemm_kernel<0><<<dim3(HH / 128, MM / 128), 256, SMEM_DYN>>>(   // 3
        (const __nv_bfloat16*)pAhi + 512, (const __nv_bfloat16*)pAlo + 512, 1024,
        (const __nv_bfloat16*)pW0hi, (const __nv_bfloat16*)pW0lo, 512,
        b0, (float*)pH, 512, 16);

    split_wcat_kernel<<<4096, 256>>>(w1, fc_w);            // 4
    bias2_kernel<<<4, 256>>>(b1, fc_b);                    // 5
    stats_partial_kernel<<<NPART, 128>>>();                // 6
    stats_finalize_kernel<<<4, 128>>>(gamma, beta);        // 7
    bnrelu_split_kernel<<<(MM * 128) / 256, 256>>>();      // 8
    init_out_kernel<<<(NB * EE + 255) / 256, 256>>>(out);  // 9

    // GEMM2: fused max of [relu_bn_h | feats] @ [w1 | fc_w]^T + (b1+fc_b)
    hmma_gemm_kernel<1><<<dim3(EE / 128, MM / 128), 256, SMEM_DYN>>>(   // 10
        (const __nv_bfloat16*)pAhi, (const __nv_bfloat16*)pAlo, 1024,
        (const __nv_bfloat16*)pWhi, (const __nv_bfloat16*)pWlo, 1024,
        (const float*)pB2, out, EE, 32);
}

// round 8
// speedup vs baseline: 1.0810x; 1.0528x over previous
#include <cuda_runtime.h>
#include <cuda_bf16.h>
#include <math_constants.h>
#include <cstdint>

#define NB   64
#define LL   577
#define DD   512
#define EE   1024
#define HH   512
#define KSEL 288
#define MM   (NB * KSEL)        // 18432 rows
#define NPART 576

// ---------------- scratch (static device globals; no allocation) -------------
__device__ __align__(16) __nv_bfloat16 g_Ahi[(size_t)MM * 1024]; // cols 0-511: relu_bn_h, 512-1023: feats
__device__ __align__(16) __nv_bfloat16 g_Alo[(size_t)MM * 1024];
__device__ __align__(16) float g_h[(size_t)MM * 512];
__device__ __align__(16) __nv_bfloat16 g_Whi[1024 * 1024];  // [e][k] k<512: w1, else fc_w
__device__ __align__(16) __nv_bfloat16 g_Wlo[1024 * 1024];
__device__ __align__(16) __nv_bfloat16 g_W0hi[512 * 512];
__device__ __align__(16) __nv_bfloat16 g_W0lo[512 * 512];
__device__ __align__(16) float g_bias2[1024];
__device__ __align__(16) float g_psum[NPART * 512];
__device__ __align__(16) float g_psq [NPART * 512];
__device__ __align__(16) float g_scale[512];
__device__ __align__(16) float g_shift[512];
__device__ int g_sel[NB * KSEL];

// ---------------- helpers ----------------------------------------------------
__device__ __forceinline__ uint32_t smem_u32(const void* p) {
    uint32_t a;
    asm("{ .reg .u64 t; cvta.to.shared.u64 t, %1; cvt.u32.u64 %0, t; }" : "=r"(a) : "l"(p));
    return a;
}
__device__ __forceinline__ void cp_async16(uint32_t saddr, const void* gaddr) {
    asm volatile("cp.async.cg.shared.global [%0], [%1], 16;" :: "r"(saddr), "l"(gaddr));
}
#define CP_COMMIT() asm volatile("cp.async.commit_group;" ::: "memory")
#define CP_WAIT1()  asm volatile("cp.async.wait_group 1;" ::: "memory")

__device__ __forceinline__ void ldsm_x4(uint32_t& r0, uint32_t& r1, uint32_t& r2, uint32_t& r3,
                                        uint32_t addr) {
    asm volatile("ldmatrix.sync.aligned.m8n8.x4.shared.b16 {%0,%1,%2,%3}, [%4];"
                 : "=r"(r0), "=r"(r1), "=r"(r2), "=r"(r3) : "r"(addr));
}
__device__ __forceinline__ void mma_bf16(float& d0, float& d1, float& d2, float& d3,
                                         uint32_t a0, uint32_t a1, uint32_t a2, uint32_t a3,
                                         uint32_t b0, uint32_t b1) {
    asm volatile("mma.sync.aligned.m16n8k16.row.col.f32.bf16.bf16.f32 "
                 "{%0,%1,%2,%3}, {%4,%5,%6,%7}, {%8,%9}, {%0,%1,%2,%3};"
                 : "+f"(d0), "+f"(d1), "+f"(d2), "+f"(d3)
                 : "r"(a0), "r"(a1), "r"(a2), "r"(a3), "r"(b0), "r"(b1));
}
__device__ __forceinline__ void atomicMaxFloat(float* addr, float val) {
    if (__float_as_int(val) >= 0) atomicMax((int*)addr, __float_as_int(val));
    else atomicMin((unsigned int*)addr, __float_as_uint(val));
}

// ---------------- small kernels ----------------------------------------------
__global__ void init_out_kernel(float* __restrict__ out) {
    int i = blockIdx.x * blockDim.x + threadIdx.x;
    if (i < NB * EE) out[i] = -CUDART_INF_F;
}

__global__ void topk_kernel(const float* __restrict__ atten) {
    __shared__ float s[LL];
    const int b = blockIdx.x;
    const float* __restrict__ row = atten + (size_t)b * LL * LL;
    for (int i = threadIdx.x; i < LL; i += blockDim.x)
        s[i] = (i == 0) ? -1.0f : row[i];
    __syncthreads();
    for (int i = threadIdx.x; i < LL; i += blockDim.x) {
        const float si = s[i];
        int rank = 0;
        #pragma unroll 4
        for (int j = 0; j < LL; ++j) {
            const float sj = s[j];
            rank += (sj > si) || (sj == si && j < i);
        }
        if (rank < KSEL) g_sel[b * KSEL + rank] = i;
    }
}

__global__ void gather_split_kernel(const float* __restrict__ basef) {
    const int t = blockIdx.x, b = blockIdx.y;
    const int n = b * KSEL + t;
    const int tok = g_sel[n];
    const float4* src = (const float4*)(basef + ((size_t)b * LL + tok) * DD);
    const float4 v = src[threadIdx.x];
    float ss = v.x * v.x + v.y * v.y + v.z * v.z + v.w * v.w;
    #pragma unroll
    for (int off = 16; off > 0; off >>= 1)
        ss += __shfl_xor_sync(0xffffffffu, ss, off);
    __shared__ float wsum[4];
    const int lane = threadIdx.x & 31, wid = threadIdx.x >> 5;
    if (lane == 0) wsum[wid] = ss;
    __syncthreads();
    const float tot = wsum[0] + wsum[1] + wsum[2] + wsum[3];
    const float inv = 1.0f / (sqrtf(tot) + 1e-8f);
    float f[4] = {v.x * inv, v.y * inv, v.z * inv, v.w * inv};
    __nv_bfloat16 hi[4], lo[4];
    #pragma unroll
    for (int i = 0; i < 4; ++i) {
        hi[i] = __float2bfloat16_rn(f[i]);
        lo[i] = __float2bfloat16_rn(f[i] - __bfloat162float(hi[i]));
    }
    const size_t off = (size_t)n * 1024 + 512 + threadIdx.x * 4;
    *(uint2*)(g_Ahi + off) = *(uint2*)hi;
    *(uint2*)(g_Alo + off) = *(uint2*)lo;
}

__global__ void split_w0_kernel(const float* __restrict__ w0) {
    const int i = blockIdx.x * blockDim.x + threadIdx.x;
    if (i >= 512 * 512) return;
    const float w = w0[i];
    const __nv_bfloat16 hi = __float2bfloat16_rn(w);
    g_W0hi[i] = hi;
    g_W0lo[i] = __float2bfloat16_rn(w - __bfloat162float(hi));
}
__global__ void split_wcat_kernel(const float* __restrict__ w1, const float* __restrict__ fcw) {
    const int i = blockIdx.x * blockDim.x + threadIdx.x;
    if (i >= 1024 * 1024) return;
    const int e = i >> 10, k = i & 1023;
    const float w = (k < 512) ? w1[e * 512 + k] : fcw[e * 512 + (k - 512)];
    const __nv_bfloat16 hi = __float2bfloat16_rn(w);
    g_Whi[i] = hi;
    g_Wlo[i] = __float2bfloat16_rn(w - __bfloat162float(hi));
}
__global__ void bias2_kernel(const float* __restrict__ b1, const float* __restrict__ bfc) {
    const int i = blockIdx.x * blockDim.x + threadIdx.x;
    if (i < 1024) g_bias2[i] = b1[i] + bfc[i];
}

// ---------------- HMMA GEMM (bf16 split, LDSM-minimized) ----------------------
// CTA tile 128x256, K-tile 32, 3-stage cp.async pipeline, 8 warps (2M x 4N),
// warp tile 64x64. Per ks: load A_hi,B_hi -> pass0; load A_lo -> pass1 (B_hi
// reused); load B_lo over B_hi regs -> pass2 (A_hi reused). 32 ldsm.x4 per
// warp per ktile for a 64x64 tile = 2.25x fewer smem bytes/output than R7
// (smem-BW was the binding constraint: tensor stuck at 48%).
// 1 CTA/SM (144KB smem, ~200 regs).
// EPI 0: out[row*ldo+col] = acc + bias[col]
// EPI 1: fused per-batch (KSEL rows) max via atomicMaxFloat into out (init -inf)
#define STAGE_BYTES 49152   // Ahi 8K | Alo 8K | Bhi 16K | Blo 16K
#define SMEM_DYN (3 * STAGE_BYTES + 128)
extern __shared__ char dynsm[];

template<int EPI>
__global__ void __launch_bounds__(256, 1) hmma_gemm_kernel(
    const __nv_bfloat16* __restrict__ aHi, const __nv_bfloat16* __restrict__ aLo, int lda,
    const __nv_bfloat16* __restrict__ bHi, const __nv_bfloat16* __restrict__ bLo, int ldb,
    const float* __restrict__ bias, float* __restrict__ out, int ldo, int KT) {
    const int tid  = threadIdx.x;
    const int lane = tid & 31;
    const int wid  = tid >> 5;
    const int warp_m = wid & 1;      // 2 warps along M (64 each)
    const int warp_n = wid >> 1;     // 4 warps along N (64 each)
    const int m0 = blockIdx.y * 128;
    const int n0 = blockIdx.x * 256;

    const uint32_t tb = (smem_u32(dynsm) + 127u) & ~127u;

    auto load_stage = [&](int stage, int kt) {
        const uint32_t sb = tb + stage * STAGE_BYTES;
        const int k0 = kt * 32;
        #pragma unroll
        for (int i = 0; i < 2; ++i) {            // A: 128 rows x 4 chunks
            const int u = tid + i * 256;
            const int row = u >> 2, c = u & 3;
            const uint32_t so = (uint32_t)(row * 64 + ((c ^ ((row >> 1) & 3)) << 4));
            const size_t ga = (size_t)(m0 + row) * lda + k0 + c * 8;
            cp_async16(sb + so,        aHi + ga);
            cp_async16(sb + 8192 + so, aLo + ga);
        }
        #pragma unroll
        for (int i = 0; i < 4; ++i) {            // B: 256 rows x 4 chunks
            const int u = tid + i * 256;
            const int row = u >> 2, c = u & 3;
            const uint32_t so = (uint32_t)(row * 64 + ((c ^ ((row >> 1) & 3)) << 4));
            const size_t gb = (size_t)(n0 + row) * ldb + k0 + c * 8;
            cp_async16(sb + 16384 + so, bHi + gb);
            cp_async16(sb + 32768 + so, bLo + gb);
        }
    };

    float acc[4][8][4];
    #pragma unroll
    for (int i = 0; i < 4; ++i)
        #pragma unroll
        for (int j = 0; j < 8; ++j)
            #pragma unroll
            for (int q = 0; q < 4; ++q) acc[i][j][q] = 0.f;

    const int aRow = warp_m * 64 + (lane & 15);
    const int aSwz = (aRow >> 1) & 3;
    const int bRow = warp_n * 64 + (lane & 15);
    const int bSwz = (bRow >> 1) & 3;
    const int cHalf = lane >> 4;

    load_stage(0, 0); CP_COMMIT();
    load_stage(1, 1); CP_COMMIT();

    for (int kt = 0; kt < KT; ++kt) {
        CP_WAIT1();
        __syncthreads();
        if (kt + 2 < KT) load_stage((kt + 2) % 3, kt + 2);
        CP_COMMIT();

        const uint32_t sb = tb + (kt % 3) * STAGE_BYTES;
        #pragma unroll
        for (int ks = 0; ks < 2; ++ks) {
            const int c = 2 * ks + cHalf;
            const uint32_t aco = (uint32_t)((c ^ aSwz) << 4);
            const uint32_t bco = (uint32_t)((c ^ bSwz) << 4);
            uint32_t af[4][4], bf[4][4], al[4][4];
            #pragma unroll
            for (int mt = 0; mt < 4; ++mt)
                ldsm_x4(af[mt][0], af[mt][1], af[mt][2], af[mt][3],
                        sb + (uint32_t)((aRow + mt * 16) * 64) + aco);
            #pragma unroll
            for (int nt = 0; nt < 4; ++nt)
                ldsm_x4(bf[nt][0], bf[nt][1], bf[nt][2], bf[nt][3],
                        sb + 16384u + (uint32_t)((bRow + nt * 16) * 64) + bco);
            // pass 0: A_hi x B_hi
            #pragma unroll
            for (int mt = 0; mt < 4; ++mt)
                #pragma unroll
                for (int n8 = 0; n8 < 8; ++n8) {
                    const int nt = n8 >> 1, nl = n8 & 1;
                    mma_bf16(acc[mt][n8][0], acc[mt][n8][1], acc[mt][n8][2], acc[mt][n8][3],
                             af[mt][0], af[mt][1], af[mt][2], af[mt][3],
                             bf[nt][nl], bf[nt][nl + 2]);
                }
            // pass 1: A_lo x B_hi
            #pragma unroll
            for (int mt = 0; mt < 4; ++mt)
                ldsm_x4(al[mt][0], al[mt][1], al[mt][2], al[mt][3],
                        sb + 8192u + (uint32_t)((aRow + mt * 16) * 64) + aco);
            #pragma unroll
            for (int mt = 0; mt < 4; ++mt)
                #pragma unroll
                for (int n8 = 0; n8 < 8; ++n8) {
                    const int nt = n8 >> 1, nl = n8 & 1;
                    mma_bf16(acc[mt][n8][0], acc[mt][n8][1], acc[mt][n8][2], acc[mt][n8][3],
                             al[mt][0], al[mt][1], al[mt][2], al[mt][3],
                             bf[nt][nl], bf[nt][nl + 2]);
                }
            // pass 2: A_hi x B_lo (reuse bf registers)
            #pragma unroll
            for (int nt = 0; nt < 4; ++nt)
                ldsm_x4(bf[nt][0], bf[nt][1], bf[nt][2], bf[nt][3],
                        sb + 32768u + (uint32_t)((bRow + nt * 16) * 64) + bco);
            #pragma unroll
            for (int mt = 0; mt < 4; ++mt)
                #pragma unroll
                for (int n8 = 0; n8 < 8; ++n8) {
                    const int nt = n8 >> 1, nl = n8 & 1;
                    mma_bf16(acc[mt][n8][0], acc[mt][n8][1], acc[mt][n8][2], acc[mt][n8][3],
                             af[mt][0], af[mt][1], af[mt][2], af[mt][3],
                             bf[nt][nl], bf[nt][nl + 2]);
                }
        }
    }

    // ------------- epilogue -------------
    const int colBase = n0 + warp_n * 64 + 2 * (lane & 3);
    const int rowBase = m0 + warp_m * 64 + (lane >> 2);
    if (EPI == 0) {
        #pragma unroll
        for (int n8 = 0; n8 < 8; ++n8) {
            const int col = colBase + n8 * 8;
            const float bv0 = __ldg(&bias[col]);
            const float bv1 = __ldg(&bias[col + 1]);
            #pragma unroll
            for (int mt = 0; mt < 4; ++mt) {
                const int r = rowBase + mt * 16;
                float2 v0 = {acc[mt][n8][0] + bv0, acc[mt][n8][1] + bv1};
                float2 v1 = {acc[mt][n8][2] + bv0, acc[mt][n8][3] + bv1};
                *(float2*)(out + (size_t)r * ldo + col) = v0;
                *(float2*)(out + (size_t)(r + 8) * ldo + col) = v1;
            }
        }
    } else {
        #pragma unroll
        for (int n8 = 0; n8 < 8; ++n8) {
            #pragma unroll
            for (int j = 0; j < 2; ++j) {
                const int col = colBase + n8 * 8 + j;
                const float bv = __ldg(&bias[col]);
                float m = -CUDART_INF_F;
                int curb = -1;
                #pragma unroll
                for (int mt = 0; mt < 4; ++mt) {
                    #pragma unroll
                    for (int half = 0; half < 2; ++half) {
                        const int r = rowBase + mt * 16 + half * 8;
                        const int bb = r / KSEL;
                        const float v = acc[mt][n8][half * 2 + j] + bv;
                        if (bb != curb) {
                            if (curb >= 0) atomicMaxFloat(&out[curb * EE + col], m);
                            curb = bb;
                            m = v;
                        } else {
                            m = fmaxf(m, v);
                        }
                    }
                }
                atomicMaxFloat(&out[curb * EE + col], m);
            }
        }
    }
}

// ---------------- BN stats / BN+ReLU+split -----------------------------------
__global__ void stats_partial_kernel() {
    const int c4 = threadIdx.x;
    const int r0 = blockIdx.x * 32;
    float4 s = {0.f, 0.f, 0.f, 0.f}, q = {0.f, 0.f, 0.f, 0.f};
    #pragma unroll 4
    for (int r = 0; r < 32; ++r) {
        float4 v = *(const float4*)(g_h + (size_t)(r0 + r) * 512 + c4 * 4);
        s.x += v.x; s.y += v.y; s.z += v.z; s.w += v.w;
        q.x += v.x * v.x; q.y += v.y * v.y; q.z += v.z * v.z; q.w += v.w * v.w;
    }
    *(float4*)(g_psum + blockIdx.x * 512 + c4 * 4) = s;
    *(float4*)(g_psq  + blockIdx.x * 512 + c4 * 4) = q;
}
__global__ void stats_finalize_kernel(const float* __restrict__ gamma,
                                      const float* __restrict__ beta) {
    const int c = blockIdx.x * 128 + threadIdx.x;
    float s = 0.f, q = 0.f;
    for (int p = 0; p < NPART; ++p) {
        s += g_psum[p * 512 + c];
        q += g_psq [p * 512 + c];
    }
    const float invN = 1.0f / (float)MM;
    const float mean = s * invN;
    const float var  = q * invN - mean * mean;
    const float sc = gamma[c] * rsqrtf(var + 1e-5f);
    g_scale[c] = sc;
    g_shift[c] = beta[c] - mean * sc;
}
__global__ void bnrelu_split_kernel() {
    const int idx = blockIdx.x * blockDim.x + threadIdx.x;
    const int n = idx >> 7, c4 = idx & 127;
    float4 v = *(const float4*)(g_h + (size_t)n * 512 + c4 * 4);
    const float4 sc = *(const float4*)(g_scale + c4 * 4);
    const float4 sh = *(const float4*)(g_shift + c4 * 4);
    float y[4];
    y[0] = fmaxf(fmaf(v.x, sc.x, sh.x), 0.f);
    y[1] = fmaxf(fmaf(v.y, sc.y, sh.y), 0.f);
    y[2] = fmaxf(fmaf(v.z, sc.z, sh.z), 0.f);
    y[3] = fmaxf(fmaf(v.w, sc.w, sh.w), 0.f);
    __nv_bfloat16 hi[4], lo[4];
    #pragma unroll
    for (int i = 0; i < 4; ++i) {
        hi[i] = __float2bfloat16_rn(y[i]);
        lo[i] = __float2bfloat16_rn(y[i] - __bfloat162float(hi[i]));
    }
    const size_t off = (size_t)n * 1024 + c4 * 4;
    *(uint2*)(g_Ahi + off) = *(uint2*)hi;
    *(uint2*)(g_Alo + off) = *(uint2*)lo;
}

// ---------------- launch ------------------------------------------------------
extern "C" void kernel_launch(void* const* d_in, const int* in_sizes, int n_in,
                              void* d_out, int out_size) {
    const float* basef = (const float*)d_in[0];
    const float* atten = (const float*)d_in[1];
    const float* fc_w  = (const float*)d_in[2];
    const float* fc_b  = (const float*)d_in[3];
    const float* w0    = (const float*)d_in[4];
    const float* b0    = (const float*)d_in[5];
    const float* gamma = (const float*)d_in[6];
    const float* beta  = (const float*)d_in[7];
    const float* w1    = (const float*)d_in[8];
    const float* b1    = (const float*)d_in[9];
    float* out = (float*)d_out;

    cudaFuncSetAttribute(hmma_gemm_kernel<0>, cudaFuncAttributeMaxDynamicSharedMemorySize, SMEM_DYN);
    cudaFuncSetAttribute(hmma_gemm_kernel<1>, cudaFuncAttributeMaxDynamicSharedMemorySize, SMEM_DYN);

    void *pAhi, *pAlo, *pW0hi, *pW0lo, *pWhi, *pWlo, *pB2, *pH;
    cudaGetSymbolAddress(&pAhi, g_Ahi);
    cudaGetSymbolAddress(&pAlo, g_Alo);
    cudaGetSymbolAddress(&pW0hi, g_W0hi);
    cudaGetSymbolAddress(&pW0lo, g_W0lo);
    cudaGetSymbolAddress(&pWhi, g_Whi);
    cudaGetSymbolAddress(&pWlo, g_Wlo);
    cudaGetSymbolAddress(&pB2, g_bias2);
    cudaGetSymbolAddress(&pH, g_h);

    // launch order chosen so index 3 (empirically what ncu captures) is gemm1
    topk_kernel<<<NB, 256>>>(atten);                       // 0
    gather_split_kernel<<<dim3(KSEL, NB), 128>>>(basef);   // 1
    split_w0_kernel<<<1024, 256>>>(w0);                    // 2

    // GEMM1: h = feats @ w0^T + b0   (N=512 -> 2 N-blocks of 256)
    hmma_gemm_kernel<0><<<dim3(HH / 256, MM / 128), 256, SMEM_DYN>>>(   // 3
        (const __nv_bfloat16*)pAhi + 512, (const __nv_bfloat16*)pAlo + 512, 1024,
        (const __nv_bfloat16*)pW0hi, (const __nv_bfloat16*)pW0lo, 512,
        b0, (float*)pH, 512, 16);

    split_wcat_kernel<<<4096, 256>>>(w1, fc_w);            // 4
    bias2_kernel<<<4, 256>>>(b1, fc_b);                    // 5
    stats_partial_kernel<<<NPART, 128>>>();                // 6
    stats_finalize_kernel<<<4, 128>>>(gamma, beta);        // 7
    bnrelu_split_kernel<<<(MM * 128) / 256, 256>>>();      // 8
    init_out_kernel<<<(NB * EE + 255) / 256, 256>>>(out);  // 9

    // GEMM2: fused max of [relu_bn_h | feats] @ [w1 | fc_w]^T + (b1+fc_b)
    hmma_gemm_kernel<1><<<dim3(EE / 256, MM / 128), 256, SMEM_DYN>>>(   // 10
        (const __nv_bfloat16*)pAhi, (const __nv_bfloat16*)pAlo, 1024,
        (const __nv_bfloat16*)pWhi, (const __nv_bfloat16*)pWlo, 1024,
        (const float*)pB2, out, EE, 32);
}